// round 5
// baseline (speedup 1.0000x reference)
#include <cuda_runtime.h>

// Problem shape (fixed by setup_inputs): B=4, C=3, H=W=256, kernel [3,1,3,3]
#define Bn   4
#define Cc   3
#define Hh   256
#define Ww   256
#define HW   (Hh * Ww)          // 65536
#define NCH  (Bn * Cc * HW)     // 786432
#define NSC  (Bn * HW)          // 262144

// Tiling: 128 tiles of 32x64 over the [B,H,W] scalar domain -> grid = 128 blocks
#define TY   32
#define TX   64
#define DW   (TX + 4)           // 68  (d tile width, halo 2)
#define TW   (TX + 2)           // 66  (t tile width, halo 1)
#define NBLK 128
#define NTHR 512
#define NB_ITERS 101            // reference scan length = NB_ITER + 1
#define TOLf 1e-6f

// -------- device scratch (no allocations allowed) --------
__device__ float g_r[NCH];
__device__ float g_p[2][NCH];
__device__ float g_ap[NCH];
__device__ float g_dscr[NSC];
__device__ float g_pd[NBLK];
__device__ float g_rr[NBLK];
__device__ unsigned int g_count = 0;
__device__ unsigned int g_gen   = 0;

// -------- software grid barrier (all 128 blocks co-resident: 128 <= #SMs) ----
__device__ __forceinline__ void gsync() {
    __syncthreads();
    if (threadIdx.x == 0) {
        volatile unsigned int* vgen = &g_gen;
        unsigned int gen = *vgen;
        __threadfence();
        if (atomicAdd(&g_count, 1u) == NBLK - 1u) {
            *((volatile unsigned int*)&g_count) = 0u;
            __threadfence();
            *vgen = gen + 1u;
        } else {
            while (*vgen == gen) { __nanosleep(64); }
        }
        __threadfence();
    }
    __syncthreads();
}

// deterministic block tree reduction; result valid on thread 0
__device__ __forceinline__ float block_reduce(float v, float* sred) {
#pragma unroll
    for (int o = 16; o > 0; o >>= 1) v += __shfl_down_sync(0xffffffffu, v, o);
    int w = threadIdx.x >> 5;
    if ((threadIdx.x & 31) == 0) sred[w] = v;
    __syncthreads();
    if (threadIdx.x < 32) {
        v = (threadIdx.x < (NTHR / 32)) ? sred[threadIdx.x] : 0.0f;
#pragma unroll
        for (int o = 8; o > 0; o >>= 1) v += __shfl_down_sync(0xffffffffu, v, o);
    }
    return v;
}

// deterministic reduction of the 128-entry partial array; every block computes
// the bitwise-identical scalar (fixed order), broadcast via shared.
__device__ __forceinline__ float reduce_arr(const float* arr, float* sred) {
    __syncthreads();                 // protect sred from previous use
    if (threadIdx.x < 32) {
        float v = 0.0f;
#pragma unroll
        for (int i = 0; i < NBLK / 32; i++)
            v += __ldcg(&arr[threadIdx.x + i * 32]);
#pragma unroll
        for (int o = 16; o > 0; o >>= 1) v += __shfl_down_sync(0xffffffffu, v, o);
        if (threadIdx.x == 0) sred[0] = v;
    }
    __syncthreads();
    float r = sred[0];
    __syncthreads();
    return r;
}

__global__ void __launch_bounds__(NTHR, 1)
cg_kernel(const float* __restrict__ mask, const float* __restrict__ yin,
          const float* __restrict__ zin,  const float* __restrict__ bein,
          const float* __restrict__ rhop, const float* __restrict__ kern,
          float* __restrict__ xout)
{
    __shared__ float sD[(TY + 4) * DW];       // d tile with halo 2
    __shared__ float sT[3][(TY + 2) * TW];    // t = P(d) tile with halo 1 (interior-masked)
    __shared__ float sRed[32];

    const int tid = threadIdx.x;
    const int bid = blockIdx.x;

    float kk[27];
#pragma unroll
    for (int i = 0; i < 27; i++) kk[i] = kern[i];
    const float rho = rhop[0];

    // tile decomposition: 4 images x (8 row-tiles x 4 col-tiles) = 128 tiles
    const int bimg = bid >> 5;
    const int tr   = (bid >> 2) & 7;
    const int tc   = bid & 3;
    const int gy0  = tr * TY;
    const int gx0  = tc * TX;
    const int sbase = bimg * HW;          // [B,H,W] base
    const int cbase = bimg * (Cc * HW);   // [B,C,H,W] base

    // t_o[q] = sum_u k_o[1+u] * d[q+u] (corr, zero-padded d), zero outside image
    auto fill_t = [&]() {
        __syncthreads();
        for (int i = tid; i < (TY + 2) * TW; i += NTHR) {
            int ly = i / TW, lx = i - ly * TW;
            int gy = gy0 + ly - 1, gx = gx0 + lx - 1;
            float t0 = 0.f, t1 = 0.f, t2 = 0.f;
            if ((unsigned)gy < Hh && (unsigned)gx < Ww) {
#pragma unroll
                for (int a = 0; a < 3; a++)
#pragma unroll
                    for (int b2 = 0; b2 < 3; b2++) {
                        float dv = sD[(ly + a) * DW + lx + b2];
                        t0 = fmaf(kk[a * 3 + b2],      dv, t0);
                        t1 = fmaf(kk[9 + a * 3 + b2],  dv, t1);
                        t2 = fmaf(kk[18 + a * 3 + b2], dv, t2);
                    }
            }
            sT[0][i] = t0; sT[1][i] = t1; sT[2][i] = t2;
        }
        __syncthreads();
    };

    // m[p] = sum_o sum_v k_o[1-v] * t_o[p+v] (true conv, t zero outside image)
    auto get_m = [&](int ly, int lx) {
        float m = 0.f;
#pragma unroll
        for (int o = 0; o < 3; o++)
#pragma unroll
            for (int a = 0; a < 3; a++)
#pragma unroll
                for (int b2 = 0; b2 < 3; b2++)
                    m = fmaf(kk[o * 9 + (2 - a) * 3 + (2 - b2)],
                             sT[o][(ly + a) * TW + lx + b2], m);
        return m;
    };

    // ================= setup S1: m_y = PT(P(y)); b = mask*m_y + rho*(z-beta);
    //                  x = b; d_x = sum_c mask*b =================
    for (int i = tid; i < (TY + 4) * DW; i += NTHR) {
        int ly = i / DW, lx = i - ly * DW;
        int gy = gy0 + ly - 2, gx = gx0 + lx - 2;
        float v = 0.f;
        if ((unsigned)gy < Hh && (unsigned)gx < Ww)
            v = yin[sbase + gy * Ww + gx];
        sD[i] = v;
    }
    fill_t();
#pragma unroll
    for (int j = 0; j < 4; j++) {
        int i = tid + j * NTHR;
        int ly = i >> 6, lx = i & 63;
        float m = get_m(ly, lx);
        int gy = gy0 + ly, gx = gx0 + lx;
        int sidx = sbase + gy * Ww + gx;
        int idx0 = cbase + gy * Ww + gx;
        float dv = 0.f;
#pragma unroll
        for (int c = 0; c < 3; c++) {
            int idx = idx0 + c * HW;
            float mk   = mask[idx];
            float bval = fmaf(mk, m, rho * (zin[idx] - bein[idx]));
            __stcg(&xout[idx], bval);
            dv = fmaf(mk, bval, dv);
        }
        __stcg(&g_dscr[sidx], dv);
    }
    gsync();

    // ================= setup S2: r = b - A(b) = (b - rho*b) - mask*m;
    //                  crit0 partials =================
    for (int i = tid; i < (TY + 4) * DW; i += NTHR) {
        int ly = i / DW, lx = i - ly * DW;
        int gy = gy0 + ly - 2, gx = gx0 + lx - 2;
        float v = 0.f;
        if ((unsigned)gy < Hh && (unsigned)gx < Ww)
            v = __ldcg(&g_dscr[sbase + gy * Ww + gx]);
        sD[i] = v;
    }
    fill_t();
    {
        float rr = 0.f;
#pragma unroll
        for (int j = 0; j < 4; j++) {
            int i = tid + j * NTHR;
            int ly = i >> 6, lx = i & 63;
            float m = get_m(ly, lx);
            int idx0 = cbase + (gy0 + ly) * Ww + (gx0 + lx);
#pragma unroll
            for (int c = 0; c < 3; c++) {
                int idx = idx0 + c * HW;
                float bval = __ldcg(&xout[idx]);
                float rv = bval - fmaf(rho, bval, mask[idx] * m);
                __stcg(&g_r[idx], rv);
                rr = fmaf(rv, rv, rr);
            }
        }
        rr = block_reduce(rr, sRed);
        if (tid == 0) __stcg(&g_rr[bid], rr);
    }
    gsync();

    // ================= CG main loop: 2 grid syncs per iteration =============
    float crit = 0.f;
    for (int k = 1; k <= NB_ITERS; k++) {
        float critprev = crit;
        crit = reduce_arr(g_rr, sRed);          // crit_{k-1}, identical in all blocks
        if (!(crit >= TOLf)) break;             // uniform freeze == reference `active`
        const bool  first = (k == 1);
        const float beta  = first ? 0.f : crit / critprev;
        const int   cur   = k & 1;
        const int   prev  = cur ^ 1;
        const float* __restrict__ pprev = g_p[prev];
        float*       __restrict__ pcur  = g_p[cur];

        // ---- phase A: p_k = r + beta*p_{k-1} (halo recompute);
        //      d = sum_c mask*p_k; fused P->PT stencil; Ap; denom partials ----
        for (int i = tid; i < (TY + 4) * DW; i += NTHR) {
            int ly = i / DW, lx = i - ly * DW;
            int gy = gy0 + ly - 2, gx = gx0 + lx - 2;
            float v = 0.f;
            if ((unsigned)gy < Hh && (unsigned)gx < Ww) {
                int idx = cbase + gy * Ww + gx;
#pragma unroll
                for (int c = 0; c < 3; c++) {
                    float pv = __ldcg(&g_r[idx]);
                    if (!first) pv = fmaf(beta, __ldcg(&pprev[idx]), pv);
                    v = fmaf(mask[idx], pv, v);
                    idx += HW;
                }
            }
            sD[i] = v;
        }
        fill_t();
        {
            float pd = 0.f;
#pragma unroll
            for (int j = 0; j < 4; j++) {
                int i = tid + j * NTHR;
                int ly = i >> 6, lx = i & 63;
                float m = get_m(ly, lx);
                int idx0 = cbase + (gy0 + ly) * Ww + (gx0 + lx);
#pragma unroll
                for (int c = 0; c < 3; c++) {
                    int idx = idx0 + c * HW;
                    float pv = __ldcg(&g_r[idx]);
                    if (!first) pv = fmaf(beta, __ldcg(&pprev[idx]), pv);
                    __stcg(&pcur[idx], pv);
                    float apv = fmaf(rho, pv, mask[idx] * m);
                    __stcg(&g_ap[idx], apv);
                    pd = fmaf(pv, apv, pd);
                }
            }
            pd = block_reduce(pd, sRed);
            if (tid == 0) __stcg(&g_pd[bid], pd);
        }
        gsync();

        // ---- phase B: alpha = crit/denom; x += alpha*p; r -= alpha*Ap;
        //      crit_k partials ----
        {
            float denom = reduce_arr(g_pd, sRed);
            float alpha = crit / denom;
            float rr = 0.f;
            int base = bid * NTHR + tid;
#pragma unroll
            for (int j = 0; j < 12; j++) {          // 786432 / (128*512) = 12
                int i = base + j * (NBLK * NTHR);
                float pv  = __ldcg(&pcur[i]);
                float apv = __ldcg(&g_ap[i]);
                __stcg(&xout[i], fmaf(alpha, pv, __ldcg(&xout[i])));
                float rv = fmaf(-alpha, apv, __ldcg(&g_r[i]));
                __stcg(&g_r[i], rv);
                rr = fmaf(rv, rv, rr);
            }
            rr = block_reduce(rr, sRed);
            if (tid == 0) __stcg(&g_rr[bid], rr);
        }
        gsync();
    }
}

extern "C" void kernel_launch(void* const* d_in, const int* in_sizes, int n_in,
                              void* d_out, int out_size) {
    (void)in_sizes; (void)n_in; (void)out_size;
    cg_kernel<<<NBLK, NTHR>>>(
        (const float*)d_in[0],   // mask  [4,3,256,256]
        (const float*)d_in[1],   // y     [4,256,256]
        (const float*)d_in[2],   // z     [4,3,256,256]
        (const float*)d_in[3],   // beta  [4,3,256,256]
        (const float*)d_in[4],   // rho   scalar
        (const float*)d_in[5],   // kernel[3,1,3,3]
        (float*)d_out);          // x     [4,3,256,256]
}

// round 8
// speedup vs baseline: 2.4397x; 2.4397x over previous
#include <cuda_runtime.h>

// Problem shape (fixed by setup_inputs): B=4, C=3, H=W=256, kernel [3,1,3,3]
#define Bn   4
#define Cc   3
#define Hh   256
#define Ww   256
#define HW   (Hh * Ww)          // 65536
#define NCH  (Bn * Cc * HW)     // 786432
#define NSC  (Bn * HW)          // 262144

// Tiling: 128 tiles of 32x64 over the [B,H,W] scalar domain -> grid = 128 blocks
#define TY   32
#define TX   64
#define DW   (TX + 4)           // 68  (d tile width, halo 2)
#define TW   (TX + 2)           // 66  (t tile width, halo 1)
#define NBLK 128
#define NTHR 512
#define PPT  ((TY * TX) / NTHR) // 4 interior points per thread
#define NRING 400               // halo-ring entries: 4*68 + 32*4
#define NB_ITERS 101
#define TOLf 1e-6f

// -------- device scratch (no allocations allowed) --------
__device__ float g_r[NCH];
__device__ float g_p[2][NCH];
__device__ float g_dscr[NSC];
__device__ float g_pd[NBLK];
__device__ float g_rr[NBLK];
__device__ unsigned int g_count = 0;
__device__ unsigned int g_gen   = 0;

// -------- software grid barrier (R5-proven form, with nanosleep) --------
__device__ __forceinline__ void gsync() {
    __syncthreads();
    if (threadIdx.x == 0) {
        volatile unsigned int* vgen = &g_gen;
        unsigned int gen = *vgen;
        __threadfence();
        if (atomicAdd(&g_count, 1u) == NBLK - 1u) {
            *((volatile unsigned int*)&g_count) = 0u;
            __threadfence();
            *vgen = gen + 1u;
        } else {
            while (*vgen == gen) { __nanosleep(64); }
        }
        __threadfence();
    }
    __syncthreads();
}

// deterministic block tree reduction; result valid on thread 0
__device__ __forceinline__ float block_reduce(float v, float* sred) {
#pragma unroll
    for (int o = 16; o > 0; o >>= 1) v += __shfl_down_sync(0xffffffffu, v, o);
    int w = threadIdx.x >> 5;
    if ((threadIdx.x & 31) == 0) sred[w] = v;
    __syncthreads();
    if (threadIdx.x < 32) {
        v = (threadIdx.x < (NTHR / 32)) ? sred[threadIdx.x] : 0.0f;
#pragma unroll
        for (int o = 8; o > 0; o >>= 1) v += __shfl_down_sync(0xffffffffu, v, o);
    }
    return v;
}

// deterministic, bitwise-identical-in-every-block reduction of 128 partials
__device__ __forceinline__ float reduce_arr(const float* arr, float* sred) {
    __syncthreads();
    if (threadIdx.x < 32) {
        float v = 0.0f;
#pragma unroll
        for (int i = 0; i < NBLK / 32; i++)
            v += __ldcg(&arr[threadIdx.x + i * 32]);
#pragma unroll
        for (int o = 16; o > 0; o >>= 1) v += __shfl_down_sync(0xffffffffu, v, o);
        if (threadIdx.x == 0) sred[0] = v;
    }
    __syncthreads();
    float r = sred[0];
    __syncthreads();
    return r;
}

__global__ void __launch_bounds__(NTHR, 1)
cg_kernel(const float* __restrict__ mask, const float* __restrict__ yin,
          const float* __restrict__ zin,  const float* __restrict__ bein,
          const float* __restrict__ rhop, const float* __restrict__ kern,
          float* __restrict__ xout)
{
    __shared__ float sD[(TY + 4) * DW];       // d tile with halo 2
    __shared__ float sT[3][(TY + 2) * TW];    // t = P(d) tile with halo 1
    __shared__ float sRed[32];

    const int tid = threadIdx.x;
    const int bid = blockIdx.x;

    float kk[27];
#pragma unroll
    for (int i = 0; i < 27; i++) kk[i] = kern[i];
    const float rho = rhop[0];

    // tile decomposition: 4 images x (8 row-tiles x 4 col-tiles) = 128 tiles
    const int bimg = bid >> 5;
    const int tr   = (bid >> 2) & 7;
    const int tc   = bid & 3;
    const int gy0  = tr * TY;
    const int gx0  = tc * TX;
    const int sbase = bimg * HW;          // [B,H,W] base
    const int cbase = bimg * (Cc * HW);   // [B,C,H,W] base

    // register-carried CG state: 4 points x 3 channels per thread
    float xv[PPT][3], rv[PPT][3], pv[PPT][3];
    float mv[PPT];                        // per-point PT(P(d_p)) of current p

    // owned point j of this thread: linear index i = tid + j*NTHR over 32x64
    // ring = within 2 of the tile edge (the only points neighbors ever read)

    // t_o[q] = sum_u k_o[1+u] * d[q+u] (corr, zero-padded d), zero outside image
    auto fill_t = [&]() {
        __syncthreads();
        for (int i = tid; i < (TY + 2) * TW; i += NTHR) {
            int ly = i / TW, lx = i - ly * TW;
            int gy = gy0 + ly - 1, gx = gx0 + lx - 1;
            float t0 = 0.f, t1 = 0.f, t2 = 0.f;
            if ((unsigned)gy < Hh && (unsigned)gx < Ww) {
#pragma unroll
                for (int a = 0; a < 3; a++)
#pragma unroll
                    for (int b2 = 0; b2 < 3; b2++) {
                        float dv = sD[(ly + a) * DW + lx + b2];
                        t0 = fmaf(kk[a * 3 + b2],      dv, t0);
                        t1 = fmaf(kk[9 + a * 3 + b2],  dv, t1);
                        t2 = fmaf(kk[18 + a * 3 + b2], dv, t2);
                    }
            }
            sT[0][i] = t0; sT[1][i] = t1; sT[2][i] = t2;
        }
        __syncthreads();
    };

    // m[p] = sum_o sum_v k_o[1-v] * t_o[p+v] (true conv, t zero outside image)
    auto get_m = [&](int ly, int lx) {
        float m = 0.f;
#pragma unroll
        for (int o = 0; o < 3; o++)
#pragma unroll
            for (int a = 0; a < 3; a++)
#pragma unroll
                for (int b2 = 0; b2 < 3; b2++)
                    m = fmaf(kk[o * 9 + (2 - a) * 3 + (2 - b2)],
                             sT[o][(ly + a) * TW + lx + b2], m);
        return m;
    };

    // ================= setup S1: m_y = PT(P(y)); b = mask*m_y + rho*(z-beta);
    //        x_reg = b; d_x = sum_c mask*b -> g_dscr (full) =================
    for (int i = tid; i < (TY + 4) * DW; i += NTHR) {
        int ly = i / DW, lx = i - ly * DW;
        int gy = gy0 + ly - 2, gx = gx0 + lx - 2;
        float v = 0.f;
        if ((unsigned)gy < Hh && (unsigned)gx < Ww)
            v = yin[sbase + gy * Ww + gx];
        sD[i] = v;
    }
    fill_t();
#pragma unroll
    for (int j = 0; j < PPT; j++) {
        int i = tid + j * NTHR;
        int ly = i >> 6, lx = i & 63;
        float m = get_m(ly, lx);
        int gy = gy0 + ly, gx = gx0 + lx;
        int idx0 = cbase + gy * Ww + gx;
        float dv = 0.f;
#pragma unroll
        for (int c = 0; c < 3; c++) {
            int idx = idx0 + c * HW;
            float mkv  = __ldg(&mask[idx]);
            float bval = fmaf(mkv, m, rho * (zin[idx] - bein[idx]));
            xv[j][c] = bval;
            dv = fmaf(mkv, bval, dv);
        }
        __stcg(&g_dscr[sbase + gy * Ww + gx], dv);
    }
    gsync();

    // ================= setup S2: r = b - A(b); r->regs (+ring store);
    //                  crit0 partials =================
    for (int i = tid; i < (TY + 4) * DW; i += NTHR) {
        int ly = i / DW, lx = i - ly * DW;
        int gy = gy0 + ly - 2, gx = gx0 + lx - 2;
        float v = 0.f;
        if ((unsigned)gy < Hh && (unsigned)gx < Ww)
            v = __ldcg(&g_dscr[sbase + gy * Ww + gx]);
        sD[i] = v;
    }
    fill_t();
    {
        float rrs = 0.f;
#pragma unroll
        for (int j = 0; j < PPT; j++) {
            int i = tid + j * NTHR;
            int ly = i >> 6, lx = i & 63;
            float m = get_m(ly, lx);
            bool ring = (ly < 2) || (ly >= TY - 2) || (lx < 2) || (lx >= TX - 2);
            int idx0 = cbase + (gy0 + ly) * Ww + (gx0 + lx);
#pragma unroll
            for (int c = 0; c < 3; c++) {
                float bval = xv[j][c];
                float r0 = bval - fmaf(rho, bval, __ldg(&mask[idx0 + c * HW]) * m);
                rv[j][c] = r0;
                pv[j][c] = 0.f;
                if (ring) __stcg(&g_r[idx0 + c * HW], r0);
                rrs = fmaf(r0, r0, rrs);
            }
        }
        rrs = block_reduce(rrs, sRed);
        if (tid == 0) __stcg(&g_rr[bid], rrs);
    }
    gsync();

    // ================= CG main loop: 2 grid syncs per iteration =============
    float crit = 0.f;
    for (int k = 1; k <= NB_ITERS; k++) {
        float critprev = crit;
        crit = reduce_arr(g_rr, sRed);          // crit_{k-1}, identical in all blocks
        if (!(crit >= TOLf)) break;             // uniform freeze == reference `active`
        const bool  first = (k == 1);
        const float beta  = first ? 0.f : crit / critprev;
        const int   cur   = k & 1;
        const float* __restrict__ pprev = g_p[cur ^ 1];
        float*       __restrict__ pcur  = g_p[cur];

        // ---- phase A step 1: interior from registers:
        //      p = r + beta*p (publish ring only); d = sum_c mask*p ----
#pragma unroll
        for (int j = 0; j < PPT; j++) {
            int i = tid + j * NTHR;
            int ly = i >> 6, lx = i & 63;
            bool ring = (ly < 2) || (ly >= TY - 2) || (lx < 2) || (lx >= TX - 2);
            int idx0 = cbase + (gy0 + ly) * Ww + (gx0 + lx);
            float dv = 0.f;
#pragma unroll
            for (int c = 0; c < 3; c++) {
                float pnew = first ? rv[j][c] : fmaf(beta, pv[j][c], rv[j][c]);
                pv[j][c] = pnew;
                dv = fmaf(__ldg(&mask[idx0 + c * HW]), pnew, dv);
                if (ring) __stcg(&pcur[idx0 + c * HW], pnew);
            }
            sD[(ly + 2) * DW + (lx + 2)] = dv;
        }

        // ---- phase A step 2: halo ring (400 entries) from published r/p ----
        if (tid < NRING) {
            int ly, lx;
            if (tid < 272) {
                int rr4 = tid / 68;
                ly = (rr4 < 2) ? rr4 : rr4 + 32;   // rows {0,1,34,35}
                lx = tid - rr4 * 68;
            } else {
                int j2 = tid - 272;
                ly = 2 + (j2 >> 2);
                int c4 = j2 & 3;
                lx = (c4 < 2) ? c4 : c4 + 64;      // cols {0,1,66,67}
            }
            int gy = gy0 + ly - 2, gx = gx0 + lx - 2;
            float dv = 0.f;
            if ((unsigned)gy < Hh && (unsigned)gx < Ww) {
                int idx = cbase + gy * Ww + gx;
#pragma unroll
                for (int c = 0; c < 3; c++) {
                    float pvh = __ldcg(&g_r[idx]);
                    if (!first) pvh = fmaf(beta, __ldcg(&pprev[idx]), pvh);
                    dv = fmaf(__ldg(&mask[idx]), pvh, dv);
                    idx += HW;
                }
            }
            sD[ly * DW + lx] = dv;
        }

        fill_t();   // __syncthreads inside covers steps 1+2

        // ---- phase A step 3: m -> regs; denom partials ----
        {
            float pd = 0.f;
#pragma unroll
            for (int j = 0; j < PPT; j++) {
                int i = tid + j * NTHR;
                int ly = i >> 6, lx = i & 63;
                float m = get_m(ly, lx);
                mv[j] = m;
                int idx0 = cbase + (gy0 + ly) * Ww + (gx0 + lx);
#pragma unroll
                for (int c = 0; c < 3; c++) {
                    float apv = fmaf(rho, pv[j][c], __ldg(&mask[idx0 + c * HW]) * m);
                    pd = fmaf(pv[j][c], apv, pd);
                }
            }
            pd = block_reduce(pd, sRed);
            if (tid == 0) __stcg(&g_pd[bid], pd);
        }
        gsync();

        // ---- phase B: pure register math; r published on ring only ----
        {
            float denom = reduce_arr(g_pd, sRed);
            float alpha = crit / denom;
            float rrs = 0.f;
#pragma unroll
            for (int j = 0; j < PPT; j++) {
                int i = tid + j * NTHR;
                int ly = i >> 6, lx = i & 63;
                bool ring = (ly < 2) || (ly >= TY - 2) || (lx < 2) || (lx >= TX - 2);
                int idx0 = cbase + (gy0 + ly) * Ww + (gx0 + lx);
#pragma unroll
                for (int c = 0; c < 3; c++) {
                    float apv = fmaf(rho, pv[j][c], __ldg(&mask[idx0 + c * HW]) * mv[j]);
                    xv[j][c] = fmaf(alpha, pv[j][c], xv[j][c]);
                    float rnew = fmaf(-alpha, apv, rv[j][c]);
                    rv[j][c] = rnew;
                    if (ring) __stcg(&g_r[idx0 + c * HW], rnew);
                    rrs = fmaf(rnew, rnew, rrs);
                }
            }
            rrs = block_reduce(rrs, sRed);
            if (tid == 0) __stcg(&g_rr[bid], rrs);
        }
        gsync();
    }

    // ================= final: write x from registers (own points) ==========
#pragma unroll
    for (int j = 0; j < PPT; j++) {
        int i = tid + j * NTHR;
        int ly = i >> 6, lx = i & 63;
        int idx0 = cbase + (gy0 + ly) * Ww + (gx0 + lx);
#pragma unroll
        for (int c = 0; c < 3; c++)
            xout[idx0 + c * HW] = xv[j][c];
    }
}

extern "C" void kernel_launch(void* const* d_in, const int* in_sizes, int n_in,
                              void* d_out, int out_size) {
    (void)in_sizes; (void)n_in; (void)out_size;
    cg_kernel<<<NBLK, NTHR>>>(
        (const float*)d_in[0],   // mask  [4,3,256,256]
        (const float*)d_in[1],   // y     [4,256,256]
        (const float*)d_in[2],   // z     [4,3,256,256]
        (const float*)d_in[3],   // beta  [4,3,256,256]
        (const float*)d_in[4],   // rho   scalar
        (const float*)d_in[5],   // kernel[3,1,3,3]
        (float*)d_out);          // x     [4,3,256,256]
}